// round 16
// baseline (speedup 1.0000x reference)
#include <cuda_runtime.h>
#include <cuda_fp16.h>
#include <math.h>
#include <stdint.h>

// ---------------- problem constants ----------------
#define IMGS 8
#define CIN  1024
#define P    1024
#define KC   28
#define KTOT 1052
#define KPAD 1088          // 17 K-stages of 64
#define COUT 2048
#define NB   4

#define STGB  32768
#define SMEMB (3 * STGB)   // 3-stage ring, 96KB -> 2 CTAs/SM

// ---------------- scratch ----------------
__device__ int    g_tilec;
__device__ __align__(16) __half g_Wh[COUT * KPAD];
__device__ __align__(16) __half g_Xh[IMGS * P * KPAD];
__device__ __align__(16) __half g_Sh[(size_t)IMGS * P * COUT];
__device__ float  g_ssum[IMGS * P];
__device__ float  g_corr[(size_t)NB * P * P];             // scaled corr, [b][t][s]
__device__ __align__(16) unsigned g_smaxu[NB * P];
__device__ __align__(16) unsigned g_tmaxu[NB * P];

__device__ const int c_dy[28] = {-3,-2,-1,0,1,2,3, -3,-2,-1,0,1,2,3, -3,-2,-1,0,1,2,3, 0,0,0,0,0,0,0};
__device__ const int c_dx[28] = {-3,-2,-1,0,1,2,3,  0, 0, 0,0,0,0,0,  3, 2, 1,0,-1,-2,-3, -3,-2,-1,0,1,2,3};

__device__ __forceinline__ const float* img_ptr(const float* src, const float* tgt, int img) {
    return (img < 4) ? (src + (size_t)img * CIN * P) : (tgt + (size_t)(img - 4) * CIN * P);
}
__device__ __forceinline__ uint32_t smem_u32(const void* p) {
    uint32_t a;
    asm("{ .reg .u64 t; cvta.to.shared.u64 t, %1; cvt.u32.u64 %0, t; }" : "=r"(a) : "l"(p));
    return a;
}
__device__ __forceinline__ void cp16(uint32_t dst, const void* src) {
    asm volatile("cp.async.cg.shared.global [%0], [%1], 16;" :: "r"(dst), "l"(src) : "memory");
}
__device__ __forceinline__ void ldsm4(uint32_t r[4], uint32_t a) {
    asm volatile("ldmatrix.sync.aligned.m8n8.x4.shared.b16 {%0,%1,%2,%3}, [%4];"
        : "=r"(r[0]), "=r"(r[1]), "=r"(r[2]), "=r"(r[3]) : "r"(a));
}
__device__ __forceinline__ void mma16816(float c[4], const uint32_t a[4], const uint32_t b[2]) {
    asm volatile("mma.sync.aligned.m16n8k16.row.col.f32.f16.f16.f32 "
        "{%0,%1,%2,%3},{%4,%5,%6,%7},{%8,%9},{%0,%1,%2,%3};"
        : "+f"(c[0]), "+f"(c[1]), "+f"(c[2]), "+f"(c[3])
        : "r"(a[0]), "r"(a[1]), "r"(a[2]), "r"(a[3]), "r"(b[0]), "r"(b[1]));
}
__device__ __forceinline__ unsigned fkey(float v) {
    unsigned b = __float_as_uint(v);
    return (b & 0x80000000u) ? ~b : (b | 0x80000000u);
}
__device__ __forceinline__ float funkey(unsigned k) {
    unsigned b = (k & 0x80000000u) ? (k & 0x7FFFFFFFu) : ~k;
    return __uint_as_float(b);
}

// ---------------- one 128x128x64 stage of MMA from swizzled smem ----------------
__device__ __forceinline__ void compute_stage(uint32_t bb, const uint32_t aoff[2],
                                              const uint32_t boff[4], float acc[2][8][4])
{
#pragma unroll
    for (int kk = 0; kk < 4; kk++) {
        uint32_t a_h[2][4];
#pragma unroll
        for (int i = 0; i < 2; i++)
            ldsm4(a_h[i], (bb + aoff[i]) ^ (kk << 5));
#pragma unroll
        for (int jj = 0; jj < 4; jj++) {
            uint32_t bh4[4];
            ldsm4(bh4, (bb + boff[jj]) ^ (kk << 5));
#pragma unroll
            for (int i = 0; i < 2; i++) {
                mma16816(acc[i][jj * 2],     a_h[i], bh4 + 0);
                mma16816(acc[i][jj * 2 + 1], a_h[i], bh4 + 2);
            }
        }
    }
}

// ---------------- GEMM mainloop: 3-stage cp.async ring, K=64/stage, swizzled smem ----------------
__device__ __forceinline__ void gemm_ml(uint32_t smb,
    const __half* Ah, const __half* Bh, int lda, int ldb, int K, float acc[2][8][4])
{
    int tid = threadIdx.x, lane = tid & 31, wid = tid >> 5;
    int wm = wid & 3, wn = wid >> 2;
    int rr = tid >> 2;
    int cq = (tid & 3) * 2;
    uint32_t ro  = (uint32_t)rr * 128;
    uint32_t sw0 = (uint32_t)((cq ^ (rr & 7)) * 16);
    uint32_t sw1 = (uint32_t)(((cq + 1) ^ (rr & 7)) * 16);
    const __half* pA0 = Ah + (size_t)rr * lda + cq * 8;
    const __half* pA1 = Ah + (size_t)(rr + 64) * lda + cq * 8;
    const __half* pB0 = Bh + (size_t)rr * ldb + cq * 8;
    const __half* pB1 = Bh + (size_t)(rr + 64) * ldb + cq * 8;

    uint32_t aoff[2], boff[4];
#pragma unroll
    for (int i = 0; i < 2; i++) {
        int row = wm * 32 + i * 16 + (lane & 15);
        aoff[i] = (uint32_t)row * 128 + (uint32_t)((((lane >> 4) ^ (lane & 7)) & 7) * 16);
    }
#pragma unroll
    for (int jj = 0; jj < 4; jj++) {
        int row = 128 + wn * 64 + jj * 16 + (lane & 7) + ((lane >> 4) & 1) * 8;
        boff[jj] = (uint32_t)row * 128 + (uint32_t)(((((lane >> 3) & 1) ^ (lane & 7)) & 7) * 16);
    }

#define ISSUE(buf, k0) do { \
        uint32_t bb = smb + (uint32_t)(buf) * STGB; \
        cp16(bb + ro + sw0,          pA0 + (k0)); \
        cp16(bb + ro + sw1,          pA0 + (k0) + 8); \
        cp16(bb + ro + 8192 + sw0,   pA1 + (k0)); \
        cp16(bb + ro + 8192 + sw1,   pA1 + (k0) + 8); \
        cp16(bb + ro + 16384 + sw0,  pB0 + (k0)); \
        cp16(bb + ro + 16384 + sw1,  pB0 + (k0) + 8); \
        cp16(bb + ro + 24576 + sw0,  pB1 + (k0)); \
        cp16(bb + ro + 24576 + sw1,  pB1 + (k0) + 8); \
        asm volatile("cp.async.commit_group;" ::: "memory"); \
    } while (0)

    int nst = K / 64;
    ISSUE(0, 0);
    ISSUE(1, 64);
    int buf = 0;
    for (int s = 0; s < nst; s++) {
        if (s + 1 < nst) { asm volatile("cp.async.wait_group 1;" ::: "memory"); }
        else             { asm volatile("cp.async.wait_group 0;" ::: "memory"); }
        __syncthreads();
        int nx = s + 2;
        if (nx < nst) ISSUE(nx % 3, nx * 64);
        compute_stage(smb + (uint32_t)buf * STGB, aoff, boff, acc);
        buf = (buf + 1 == 3) ? 0 : buf + 1;
    }
#undef ISSUE
}

// ---------------- kernel 1: pad W + zero scratch ----------------
__global__ void k_wpad(const float* __restrict__ W) {
    int gid = blockIdx.x * 256 + threadIdx.x;
    if (gid < IMGS * P) g_ssum[gid] = 0.f;
    if (gid < NB * P) { g_smaxu[gid] = 0u; g_tmaxu[gid] = 0u; }
    if (gid == 0) g_tilec = 0;
    size_t base = ((size_t)gid) * 8;
#pragma unroll
    for (int u = 0; u < 8; u++) {
        size_t idx = base + u;
        int o = (int)(idx / KPAD);
        int k = (int)(idx - (size_t)o * KPAD);
        float v = (k < KTOT) ? W[(size_t)o * KTOT + k] : 0.f;
        g_Wh[idx] = __float2half_rn(v);
    }
}

// ---------------- kernel 2: fused ctx + norms + fp16 transpose into g_Xh ----------------
__global__ void __launch_bounds__(256) k_pre(const float* __restrict__ src, const float* __restrict__ tgt) {
    int img = blockIdx.x, y = blockIdx.y;
    const float* f = img_ptr(src, tgt, img);
    int lane = threadIdx.x & 31, w = threadIdx.x >> 5;
    __shared__ float tile[8][7][32];
    __shared__ float red[28][8][32];
    __shared__ float redn[7][8][32];
    __shared__ float invl[7][32];
    __shared__ __half xst[2][8][32];
    float acc[28];
    float accn[7];
#pragma unroll
    for (int k = 0; k < 28; k++) acc[k] = 0.f;
#pragma unroll
    for (int d = 0; d < 7; d++) accn[d] = 0.f;

    __half* Xrow = g_Xh + ((size_t)img * P + y * 32) * KPAD;
    int pl = threadIdx.x >> 3, cl = threadIdx.x & 7;

    for (int it = 0; it < 128; it++) {
        int c = it * 8 + w;
#pragma unroll
        for (int dy = 0; dy < 7; dy++) {
            int yy = y + dy - 3;
            float v = (yy >= 0 && yy < 32) ? f[c * P + yy * 32 + lane] : 0.f;
            tile[w][dy][lane] = v;
            accn[dy] = fmaf(v, v, accn[dy]);
        }
        __syncwarp();
        float v0 = tile[w][3][lane];
        xst[it & 1][w][lane] = __float2half_rn(v0);
#pragma unroll
        for (int k = 0; k < 28; k++) {
            int xx = lane + c_dx[k];
            float v = (xx >= 0 && xx < 32) ? tile[w][c_dy[k] + 3][xx] : 0.f;
            acc[k] = fmaf(v0, v, acc[k]);
        }
        __syncthreads();
        Xrow[(size_t)pl * KPAD + it * 8 + cl] = xst[it & 1][cl][pl];
    }
#pragma unroll
    for (int k = 0; k < 28; k++) red[k][w][lane] = acc[k];
#pragma unroll
    for (int d = 0; d < 7; d++) redn[d][w][lane] = accn[d];
    __syncthreads();

    if (threadIdx.x < 7 * 32) {
        int d = threadIdx.x >> 5, x = threadIdx.x & 31;
        float s = 0.f;
#pragma unroll
        for (int i = 0; i < 8; i++) s += redn[d][i][x];
        invl[d][x] = 1.f / fmaxf(sqrtf(s), 1e-12f);
    }
    __syncthreads();

    // ctx channels (1024..1051) + zero pad (1052..1087)
    for (int idx = threadIdx.x; idx < 64 * 32; idx += 256) {
        int k = idx >> 5, x = idx & 31;
        float o = 0.f;
        if (k < KC) {
            float s = 0.f;
#pragma unroll
            for (int i = 0; i < 8; i++) s += red[k][i][x];
            int yy = y + c_dy[k], xx = x + c_dx[k];
            if (yy >= 0 && yy < 32 && xx >= 0 && xx < 32)
                o = s * invl[3][x] * invl[c_dy[k] + 3][xx];
        }
        if (CIN + k < KPAD)
            Xrow[(size_t)x * KPAD + CIN + k] = __float2half_rn(o);
    }
}

// ---------------- conv GEMM: persistent, atomic work-stealing ----------------
__global__ void __launch_bounds__(256, 2) k_conv(const float* __restrict__ bias) {
    extern __shared__ char smc[];
    __shared__ float sss[128];
    __shared__ int tsh;
    uint32_t smb = (smem_u32(smc) + 127u) & ~127u;
    int lane = threadIdx.x & 31, wid = threadIdx.x >> 5, wm = wid & 3, wn = wid >> 2;

    for (;;) {
        if (threadIdx.x == 0) tsh = atomicAdd(&g_tilec, 1);
        __syncthreads();
        int t = tsh;
        if (t >= 1024) break;
        int img = t >> 7, r = t & 127;
        int bm = (r >> 4) * 128, bn = (r & 15) * 128;
        const __half* Ah = g_Xh + ((size_t)img * P + bm) * KPAD;
        const __half* Bh = g_Wh + (size_t)bn * KPAD;
        float acc[2][8][4] = {};
        gemm_ml(smb, Ah, Bh, KPAD, KPAD, KPAD, acc);

        if (threadIdx.x < 128) sss[threadIdx.x] = 0.f;
        __syncthreads();

        __half* Shp = g_Sh + (size_t)img * P * COUT;
#pragma unroll
        for (int i = 0; i < 2; i++) {
            int pl0 = wm * 32 + i * 16 + (lane >> 2);
            int p0 = bm + pl0;
            float q0 = 0.f, q1 = 0.f;
#pragma unroll
            for (int j = 0; j < 8; j++) {
                int o = bn + wn * 64 + j * 8 + 2 * (lane & 3);
                float2 bb = *(const float2*)(bias + o);
                float a0 = fmaxf(acc[i][j][0] + bb.x, 0.f);
                float a1 = fmaxf(acc[i][j][1] + bb.y, 0.f);
                float a2 = fmaxf(acc[i][j][2] + bb.x, 0.f);
                float a3 = fmaxf(acc[i][j][3] + bb.y, 0.f);
                q0 = fmaf(a0, a0, fmaf(a1, a1, q0));
                q1 = fmaf(a2, a2, fmaf(a3, a3, q1));
                *(__half2*)(Shp + (size_t)p0 * COUT + o)       = __halves2half2(__float2half_rn(a0), __float2half_rn(a1));
                *(__half2*)(Shp + (size_t)(p0 + 8) * COUT + o) = __halves2half2(__float2half_rn(a2), __float2half_rn(a3));
            }
            atomicAdd(&sss[pl0], q0);
            atomicAdd(&sss[pl0 + 8], q1);
        }
        __syncthreads();
        if (threadIdx.x < 128) atomicAdd(&g_ssum[img * P + bm + threadIdx.x], sss[threadIdx.x]);
        __syncthreads();
    }
}

// ---------------- corr GEMM (plain fp16): scaled corr [b][t][s] + fused tile maxes ----------------
__global__ void __launch_bounds__(256, 2) k_corr() {
    extern __shared__ char smc[];
    __shared__ unsigned su[128], tu[128];
    uint32_t smb = (smem_u32(smc) + 127u) & ~127u;
    int b = blockIdx.z, bm = blockIdx.y * 128, bn = blockIdx.x * 128;
    const __half* Ah = g_Sh + ((size_t)b * P + bm) * COUT;
    const __half* Bh = g_Sh + ((size_t)(4 + b) * P + bn) * COUT;
    float acc[2][8][4] = {};
    gemm_ml(smb, Ah, Bh, COUT, COUT, COUT, acc);

    if (threadIdx.x < 128) { su[threadIdx.x] = 0u; tu[threadIdx.x] = 0u; }
    __syncthreads();

    int lane = threadIdx.x & 31, wid = threadIdx.x >> 5, wm = wid & 3, wn = wid >> 2;
    const float* ssums = g_ssum + b * P;
    const float* ssumt = g_ssum + (4 + b) * P;
    float* C = g_corr + (size_t)b * P * P;
#pragma unroll
    for (int i = 0; i < 2; i++) {
        int sl0 = wm * 32 + i * 16 + (lane >> 2);
        int s0 = bm + sl0;
        float is0 = rsqrtf(ssums[s0] + 1e-6f), is1 = rsqrtf(ssums[s0 + 8] + 1e-6f);
        unsigned ks0 = 0u, ks1 = 0u;
#pragma unroll
        for (int j = 0; j < 8; j++) {
            int tl0 = wn * 64 + j * 8 + 2 * (lane & 3);
            int t0 = bn + tl0;
            float it0 = rsqrtf(ssumt[t0] + 1e-6f), it1 = rsqrtf(ssumt[t0 + 1] + 1e-6f);
            float c00 = acc[i][j][0] * is0 * it0;
            float c01 = acc[i][j][1] * is0 * it1;
            float c10 = acc[i][j][2] * is1 * it0;
            float c11 = acc[i][j][3] * is1 * it1;
            C[(size_t)t0 * P + s0]           = c00;
            C[(size_t)(t0 + 1) * P + s0]     = c01;
            C[(size_t)t0 * P + s0 + 8]       = c10;
            C[(size_t)(t0 + 1) * P + s0 + 8] = c11;
            unsigned k00 = fkey(c00), k01 = fkey(c01), k10 = fkey(c10), k11 = fkey(c11);
            ks0 = max(ks0, max(k00, k01));
            ks1 = max(ks1, max(k10, k11));
            atomicMax(&tu[tl0],     max(k00, k10));
            atomicMax(&tu[tl0 + 1], max(k01, k11));
        }
        atomicMax(&su[sl0], ks0);
        atomicMax(&su[sl0 + 8], ks1);
    }
    __syncthreads();
    if (threadIdx.x < 128) {
        atomicMax(&g_smaxu[b * P + bm + threadIdx.x], su[threadIdx.x]);
        atomicMax(&g_tmaxu[b * P + bn + threadIdx.x], tu[threadIdx.x]);
    }
}

// ---------------- fused filter + resize + softmax + soft-argmax + flow ----------------
__global__ void __launch_bounds__(256) k_flow(float* __restrict__ out) {
    int tx = blockIdx.x, ty = blockIdx.y, b = blockIdx.z;
    int tid = threadIdx.x;
    const float sc = 31.f / 63.f;
    float fy = ty * sc; int y0 = (int)fy; int y1 = min(y0 + 1, 31); float wy = fy - (float)y0;
    float fx = tx * sc; int x0 = (int)fx; int x1 = min(x0 + 1, 31); float wx = fx - (float)x0;
    int t00 = y0 * 32 + x0, t01 = y0 * 32 + x1, t10 = y1 * 32 + x0, t11 = y1 * 32 + x1;
    const float* C = g_corr + (size_t)b * P * P;
    const float* r00 = C + (size_t)t00 * P;
    const float* r01 = C + (size_t)t01 * P;
    const float* r10 = C + (size_t)t10 * P;
    const float* r11 = C + (size_t)t11 * P;
    float tm00 = funkey(g_tmaxu[b * P + t00]); if (tm00 == 0.f) tm00 = 1e-30f;
    float tm01 = funkey(g_tmaxu[b * P + t01]); if (tm01 == 0.f) tm01 = 1e-30f;
    float tm10 = funkey(g_tmaxu[b * P + t10]); if (tm10 == 0.f) tm10 = 1e-30f;
    float tm11 = funkey(g_tmaxu[b * P + t11]); if (tm11 == 0.f) tm11 = 1e-30f;
    float ww00 = (1.f - wy) * (1.f - wx) / tm00;
    float ww01 = (1.f - wy) * wx         / tm01;
    float ww10 = wy * (1.f - wx)         / tm10;
    float ww11 = wy * wx                 / tm11;

    __shared__ float m[P];
    __shared__ float rowt[32][64];
    __shared__ float rd[8], rs[8], rx[8], ry[8];

    float mx;
    {
        int s0 = tid * 4;
        float4 v00 = *(const float4*)(r00 + s0);
        float4 v01 = *(const float4*)(r01 + s0);
        float4 v10 = *(const float4*)(r10 + s0);
        float4 v11 = *(const float4*)(r11 + s0);
        uint4 km = *(const uint4*)(g_smaxu + (size_t)b * P + s0);
        float sm0 = funkey(km.x); if (sm0 == 0.f) sm0 = 1e-30f;
        float sm1 = funkey(km.y); if (sm1 == 0.f) sm1 = 1e-30f;
        float sm2 = funkey(km.z); if (sm2 == 0.f) sm2 = 1e-30f;
        float sm3 = funkey(km.w); if (sm3 == 0.f) sm3 = 1e-30f;
        float4 mv;
        mv.x = __fdividef(ww00 * v00.x * v00.x * v00.x + ww01 * v01.x * v01.x * v01.x
              + ww10 * v10.x * v10.x * v10.x + ww11 * v11.x * v11.x * v11.x, sm0);
        mv.y = __fdividef(ww00 * v00.y * v00.y * v00.y + ww01 * v01.y * v01.y * v01.y
              + ww10 * v10.y * v10.y * v10.y + ww11 * v11.y * v11.y * v11.y, sm1);
        mv.z = __fdividef(ww00 * v00.z * v00.z * v00.z + ww01 * v01.z * v01.z * v01.z
              + ww10 * v10.z * v10.z * v10.z + ww11 * v11.z * v11.z * v11.z, sm2);
        mv.w = __fdividef(ww00 * v00.w * v00.w * v00.w + ww01 * v01.w * v01.w * v01.w
              + ww10 * v10.w * v10.w * v10.w + ww11 * v11.w * v11.w * v11.w, sm3);
        *(float4*)(m + s0) = mv;
        mx = fmaxf(fmaxf(mv.x, mv.y), fmaxf(mv.z, mv.w));
    }
#pragma unroll
    for (int o = 16; o > 0; o >>= 1) mx = fmaxf(mx, __shfl_xor_sync(0xffffffffu, mx, o));
    if ((tid & 31) == 0) rd[tid >> 5] = mx;
    __syncthreads();

    for (int idx = tid; idx < 32 * 64; idx += 256) {
        int y = idx >> 6, j = idx & 63;
        float gx = j * sc; int xx0 = (int)gx; int xx1 = min(xx0 + 1, 31); float bq = gx - (float)xx0;
        float u0 = m[y * 32 + xx0];
        rowt[y][j] = u0 + bq * (m[y * 32 + xx1] - u0);
    }
    float M = -INFINITY;
#pragma unroll
    for (int i = 0; i < 8; i++) M = fmaxf(M, rd[i]);
    __syncthreads();

    int j = tid & 63, i0 = tid >> 6;
    float xn = -1.f + j * (2.f / 63.f);
    float sum = 0.f, sx = 0.f, sy = 0.f;
#pragma unroll
    for (int k2 = 0; k2 < 16; k2++) {
        int i = i0 + k2 * 4;
        float gy = i * sc; int yy0 = (int)gy; int yy1 = min(yy0 + 1, 31); float a = gy - (float)yy0;
        float u0 = rowt[yy0][j];
        float v = u0 + a * (rowt[yy1][j] - u0);
        float e = __expf((v - M) * 50.f);
        sum += e;
        sx = fmaf(e, xn, sx);
        sy = fmaf(e, -1.f + i * (2.f / 63.f), sy);
    }
#pragma unroll
    for (int o = 16; o > 0; o >>= 1) {
        sum += __shfl_xor_sync(0xffffffffu, sum, o);
        sx  += __shfl_xor_sync(0xffffffffu, sx,  o);
        sy  += __shfl_xor_sync(0xffffffffu, sy,  o);
    }
    if ((tid & 31) == 0) { rs[tid >> 5] = sum; rx[tid >> 5] = sx; ry[tid >> 5] = sy; }
    __syncthreads();
    if (tid == 0) {
        float S = 0.f, X = 0.f, Y = 0.f;
#pragma unroll
        for (int i = 0; i < 8; i++) { S += rs[i]; X += rx[i]; Y += ry[i]; }
        float gx_ = X / S, gy_ = Y / S;
        out[(size_t)b * 8192 + (size_t)ty * 64 + tx]        = (gx_ + 1.f) * 31.5f - (float)tx;
        out[(size_t)b * 8192 + 4096 + (size_t)ty * 64 + tx] = (gy_ + 1.f) * 31.5f - (float)ty;
    }
}

// ---------------- launch ----------------
extern "C" void kernel_launch(void* const* d_in, const int* in_sizes, int n_in,
                              void* d_out, int out_size) {
    const float* src  = (const float*)d_in[0];
    const float* tgt  = (const float*)d_in[1];
    const float* W    = (const float*)d_in[2];
    const float* bias = (const float*)d_in[3];
    float* out = (float*)d_out;

    cudaFuncSetAttribute(k_conv, cudaFuncAttributeMaxDynamicSharedMemorySize, SMEMB);
    cudaFuncSetAttribute(k_corr, cudaFuncAttributeMaxDynamicSharedMemorySize, SMEMB);

    k_wpad <<<1088, 256>>>(W);
    k_pre  <<<dim3(8, 32), 256>>>(src, tgt);
    k_conv <<<296, 256, SMEMB>>>(bias);
    k_corr <<<dim3(8, 8, 4), 256, SMEMB>>>();
    k_flow <<<dim3(64, 64, 4), 256>>>(out);
}

// round 17
// speedup vs baseline: 1.1683x; 1.1683x over previous
#include <cuda_runtime.h>
#include <cuda_fp16.h>
#include <math.h>
#include <stdint.h>

// ---------------- problem constants ----------------
#define IMGS 8
#define CIN  1024
#define P    1024
#define KC   28
#define KTOT 1052
#define KPAD 1088          // 17 K-stages of 64
#define COUT 2048
#define NB   4

#define STGB  32768
#define SMEMB (3 * STGB)   // 3-stage ring, 96KB -> 2 CTAs/SM

// k_pre staging: 32 positions x 1090-half pitch (conflict-free: 545 % 32 == 1)
#define XPITCH 1090
#define PREB   (32 * XPITCH * 2)

// ---------------- scratch ----------------
__device__ int    g_tilec;
__device__ __align__(16) __half g_Wh[COUT * KPAD];
__device__ __align__(16) __half g_Xh[IMGS * P * KPAD];
__device__ __align__(16) __half g_Sh[(size_t)IMGS * P * COUT];
__device__ float  g_ssum[IMGS * P];
__device__ float  g_corr[(size_t)NB * P * P];             // scaled corr, [b][t][s]
__device__ __align__(16) unsigned g_smaxu[NB * P];
__device__ __align__(16) unsigned g_tmaxu[NB * P];

__device__ const int c_dy[28] = {-3,-2,-1,0,1,2,3, -3,-2,-1,0,1,2,3, -3,-2,-1,0,1,2,3, 0,0,0,0,0,0,0};
__device__ const int c_dx[28] = {-3,-2,-1,0,1,2,3,  0, 0, 0,0,0,0,0,  3, 2, 1,0,-1,-2,-3, -3,-2,-1,0,1,2,3};

__device__ __forceinline__ const float* img_ptr(const float* src, const float* tgt, int img) {
    return (img < 4) ? (src + (size_t)img * CIN * P) : (tgt + (size_t)(img - 4) * CIN * P);
}
__device__ __forceinline__ uint32_t smem_u32(const void* p) {
    uint32_t a;
    asm("{ .reg .u64 t; cvta.to.shared.u64 t, %1; cvt.u32.u64 %0, t; }" : "=r"(a) : "l"(p));
    return a;
}
__device__ __forceinline__ void cp16(uint32_t dst, const void* src) {
    asm volatile("cp.async.cg.shared.global [%0], [%1], 16;" :: "r"(dst), "l"(src) : "memory");
}
__device__ __forceinline__ void ldsm4(uint32_t r[4], uint32_t a) {
    asm volatile("ldmatrix.sync.aligned.m8n8.x4.shared.b16 {%0,%1,%2,%3}, [%4];"
        : "=r"(r[0]), "=r"(r[1]), "=r"(r[2]), "=r"(r[3]) : "r"(a));
}
__device__ __forceinline__ void mma16816(float c[4], const uint32_t a[4], const uint32_t b[2]) {
    asm volatile("mma.sync.aligned.m16n8k16.row.col.f32.f16.f16.f32 "
        "{%0,%1,%2,%3},{%4,%5,%6,%7},{%8,%9},{%0,%1,%2,%3};"
        : "+f"(c[0]), "+f"(c[1]), "+f"(c[2]), "+f"(c[3])
        : "r"(a[0]), "r"(a[1]), "r"(a[2]), "r"(a[3]), "r"(b[0]), "r"(b[1]));
}
__device__ __forceinline__ unsigned fkey(float v) {
    unsigned b = __float_as_uint(v);
    return (b & 0x80000000u) ? ~b : (b | 0x80000000u);
}
__device__ __forceinline__ float funkey(unsigned k) {
    unsigned b = (k & 0x80000000u) ? (k & 0x7FFFFFFFu) : ~k;
    return __uint_as_float(b);
}

// ---------------- one 128x128x64 stage of MMA from swizzled smem ----------------
__device__ __forceinline__ void compute_stage(uint32_t bb, const uint32_t aoff[2],
                                              const uint32_t boff[4], float acc[2][8][4])
{
#pragma unroll
    for (int kk = 0; kk < 4; kk++) {
        uint32_t a_h[2][4];
#pragma unroll
        for (int i = 0; i < 2; i++)
            ldsm4(a_h[i], (bb + aoff[i]) ^ (kk << 5));
#pragma unroll
        for (int jj = 0; jj < 4; jj++) {
            uint32_t bh4[4];
            ldsm4(bh4, (bb + boff[jj]) ^ (kk << 5));
#pragma unroll
            for (int i = 0; i < 2; i++) {
                mma16816(acc[i][jj * 2],     a_h[i], bh4 + 0);
                mma16816(acc[i][jj * 2 + 1], a_h[i], bh4 + 2);
            }
        }
    }
}

// ---------------- GEMM mainloop: 3-stage cp.async ring, K=64/stage, swizzled smem ----------------
__device__ __forceinline__ void gemm_ml(uint32_t smb,
    const __half* Ah, const __half* Bh, int lda, int ldb, int K, float acc[2][8][4])
{
    int tid = threadIdx.x, lane = tid & 31, wid = tid >> 5;
    int wm = wid & 3, wn = wid >> 2;
    int rr = tid >> 2;
    int cq = (tid & 3) * 2;
    uint32_t ro  = (uint32_t)rr * 128;
    uint32_t sw0 = (uint32_t)((cq ^ (rr & 7)) * 16);
    uint32_t sw1 = (uint32_t)(((cq + 1) ^ (rr & 7)) * 16);
    const __half* pA0 = Ah + (size_t)rr * lda + cq * 8;
    const __half* pA1 = Ah + (size_t)(rr + 64) * lda + cq * 8;
    const __half* pB0 = Bh + (size_t)rr * ldb + cq * 8;
    const __half* pB1 = Bh + (size_t)(rr + 64) * ldb + cq * 8;

    uint32_t aoff[2], boff[4];
#pragma unroll
    for (int i = 0; i < 2; i++) {
        int row = wm * 32 + i * 16 + (lane & 15);
        aoff[i] = (uint32_t)row * 128 + (uint32_t)((((lane >> 4) ^ (lane & 7)) & 7) * 16);
    }
#pragma unroll
    for (int jj = 0; jj < 4; jj++) {
        int row = 128 + wn * 64 + jj * 16 + (lane & 7) + ((lane >> 4) & 1) * 8;
        boff[jj] = (uint32_t)row * 128 + (uint32_t)(((((lane >> 3) & 1) ^ (lane & 7)) & 7) * 16);
    }

#define ISSUE(buf, k0) do { \
        uint32_t bb = smb + (uint32_t)(buf) * STGB; \
        cp16(bb + ro + sw0,          pA0 + (k0)); \
        cp16(bb + ro + sw1,          pA0 + (k0) + 8); \
        cp16(bb + ro + 8192 + sw0,   pA1 + (k0)); \
        cp16(bb + ro + 8192 + sw1,   pA1 + (k0) + 8); \
        cp16(bb + ro + 16384 + sw0,  pB0 + (k0)); \
        cp16(bb + ro + 16384 + sw1,  pB0 + (k0) + 8); \
        cp16(bb + ro + 24576 + sw0,  pB1 + (k0)); \
        cp16(bb + ro + 24576 + sw1,  pB1 + (k0) + 8); \
        asm volatile("cp.async.commit_group;" ::: "memory"); \
    } while (0)

    int nst = K / 64;
    ISSUE(0, 0);
    ISSUE(1, 64);
    int buf = 0;
    for (int s = 0; s < nst; s++) {
        if (s + 1 < nst) { asm volatile("cp.async.wait_group 1;" ::: "memory"); }
        else             { asm volatile("cp.async.wait_group 0;" ::: "memory"); }
        __syncthreads();
        int nx = s + 2;
        if (nx < nst) ISSUE(nx % 3, nx * 64);
        compute_stage(smb + (uint32_t)buf * STGB, aoff, boff, acc);
        buf = (buf + 1 == 3) ? 0 : buf + 1;
    }
#undef ISSUE
}

// ---------------- kernel 1: pad W + zero scratch ----------------
__global__ void k_wpad(const float* __restrict__ W) {
    int gid = blockIdx.x * 256 + threadIdx.x;
    if (gid < IMGS * P) g_ssum[gid] = 0.f;
    if (gid < NB * P) { g_smaxu[gid] = 0u; g_tmaxu[gid] = 0u; }
    if (gid == 0) g_tilec = 0;
    size_t base = ((size_t)gid) * 8;
#pragma unroll
    for (int u = 0; u < 8; u++) {
        size_t idx = base + u;
        int o = (int)(idx / KPAD);
        int k = (int)(idx - (size_t)o * KPAD);
        float v = (k < KTOT) ? W[(size_t)o * KTOT + k] : 0.f;
        g_Wh[idx] = __float2half_rn(v);
    }
}

// ---------------- kernel 2: fused ctx + norms + fp16 transpose (barrier-free mainloop) ----------------
__global__ void __launch_bounds__(256) k_pre(const float* __restrict__ src, const float* __restrict__ tgt) {
    extern __shared__ __half xst[];     // [32][XPITCH]
    int img = blockIdx.x, y = blockIdx.y;
    const float* f = img_ptr(src, tgt, img);
    int lane = threadIdx.x & 31, w = threadIdx.x >> 5;
    __shared__ float tile[8][7][32];
    __shared__ float red[28][8][32];
    __shared__ float redn[7][8][32];
    __shared__ float invl[7][32];
    float acc[28];
    float accn[7];
#pragma unroll
    for (int k = 0; k < 28; k++) acc[k] = 0.f;
#pragma unroll
    for (int d = 0; d < 7; d++) accn[d] = 0.f;

    for (int it = 0; it < 128; it++) {
        int c = it * 8 + w;
#pragma unroll
        for (int dy = 0; dy < 7; dy++) {
            int yy = y + dy - 3;
            float v = (yy >= 0 && yy < 32) ? f[c * P + yy * 32 + lane] : 0.f;
            tile[w][dy][lane] = v;
            accn[dy] = fmaf(v, v, accn[dy]);
        }
        __syncwarp();
        float v0 = tile[w][3][lane];
        xst[lane * XPITCH + c] = __float2half_rn(v0);    // conflict-free (545%32==1)
#pragma unroll
        for (int k = 0; k < 28; k++) {
            int xx = lane + c_dx[k];
            float v = (xx >= 0 && xx < 32) ? tile[w][c_dy[k] + 3][xx] : 0.f;
            acc[k] = fmaf(v0, v, acc[k]);
        }
        __syncwarp();
    }
#pragma unroll
    for (int k = 0; k < 28; k++) red[k][w][lane] = acc[k];
#pragma unroll
    for (int d = 0; d < 7; d++) redn[d][w][lane] = accn[d];
    __syncthreads();

    if (threadIdx.x < 7 * 32) {
        int d = threadIdx.x >> 5, x = threadIdx.x & 31;
        float s = 0.f;
#pragma unroll
        for (int i = 0; i < 8; i++) s += redn[d][i][x];
        invl[d][x] = 1.f / fmaxf(sqrtf(s), 1e-12f);
    }
    __syncthreads();

    // ctx channels (1024..1051) + zero pad (1052..1087), into staging
    for (int idx = threadIdx.x; idx < 64 * 32; idx += 256) {
        int k = idx >> 5, x = idx & 31;
        float o = 0.f;
        if (k < KC) {
            float s = 0.f;
#pragma unroll
            for (int i = 0; i < 8; i++) s += red[k][i][x];
            int yy = y + c_dy[k], xx = x + c_dx[k];
            if (yy >= 0 && yy < 32 && xx >= 0 && xx < 32)
                o = s * invl[3][x] * invl[c_dy[k] + 3][xx];
        }
        xst[x * XPITCH + CIN + k] = __float2half_rn(o);
    }
    __syncthreads();

    // coalesced flush: half2 units; 544 = 17*32 so each warp stays in one p-row
    __half* Xrow = g_Xh + ((size_t)img * P + y * 32) * KPAD;
    for (int idx = threadIdx.x; idx < 32 * (KPAD / 2); idx += 256) {
        int p = idx / (KPAD / 2), cc = idx - p * (KPAD / 2);
        *(__half2*)(Xrow + (size_t)p * KPAD + 2 * cc) = *(__half2*)(xst + p * XPITCH + 2 * cc);
    }
}

// ---------------- conv GEMM: persistent, atomic work-stealing ----------------
__global__ void __launch_bounds__(256, 2) k_conv(const float* __restrict__ bias) {
    extern __shared__ char smc[];
    __shared__ float sss[128];
    __shared__ int tsh;
    uint32_t smb = (smem_u32(smc) + 127u) & ~127u;
    int lane = threadIdx.x & 31, wid = threadIdx.x >> 5, wm = wid & 3, wn = wid >> 2;

    for (;;) {
        if (threadIdx.x == 0) tsh = atomicAdd(&g_tilec, 1);
        __syncthreads();
        int t = tsh;
        if (t >= 1024) break;
        int img = t >> 7, r = t & 127;
        int bm = (r >> 4) * 128, bn = (r & 15) * 128;
        const __half* Ah = g_Xh + ((size_t)img * P + bm) * KPAD;
        const __half* Bh = g_Wh + (size_t)bn * KPAD;
        float acc[2][8][4] = {};
        gemm_ml(smb, Ah, Bh, KPAD, KPAD, KPAD, acc);

        if (threadIdx.x < 128) sss[threadIdx.x] = 0.f;
        __syncthreads();

        __half* Shp = g_Sh + (size_t)img * P * COUT;
#pragma unroll
        for (int i = 0; i < 2; i++) {
            int pl0 = wm * 32 + i * 16 + (lane >> 2);
            int p0 = bm + pl0;
            float q0 = 0.f, q1 = 0.f;
#pragma unroll
            for (int j = 0; j < 8; j++) {
                int o = bn + wn * 64 + j * 8 + 2 * (lane & 3);
                float2 bb = *(const float2*)(bias + o);
                float a0 = fmaxf(acc[i][j][0] + bb.x, 0.f);
                float a1 = fmaxf(acc[i][j][1] + bb.y, 0.f);
                float a2 = fmaxf(acc[i][j][2] + bb.x, 0.f);
                float a3 = fmaxf(acc[i][j][3] + bb.y, 0.f);
                q0 = fmaf(a0, a0, fmaf(a1, a1, q0));
                q1 = fmaf(a2, a2, fmaf(a3, a3, q1));
                *(__half2*)(Shp + (size_t)p0 * COUT + o)       = __halves2half2(__float2half_rn(a0), __float2half_rn(a1));
                *(__half2*)(Shp + (size_t)(p0 + 8) * COUT + o) = __halves2half2(__float2half_rn(a2), __float2half_rn(a3));
            }
            atomicAdd(&sss[pl0], q0);
            atomicAdd(&sss[pl0 + 8], q1);
        }
        __syncthreads();
        if (threadIdx.x < 128) atomicAdd(&g_ssum[img * P + bm + threadIdx.x], sss[threadIdx.x]);
        __syncthreads();
    }
}

// ---------------- corr GEMM (plain fp16): scaled corr [b][t][s] + fused tile maxes ----------------
__global__ void __launch_bounds__(256, 2) k_corr() {
    extern __shared__ char smc[];
    __shared__ unsigned su[128], tu[128];
    uint32_t smb = (smem_u32(smc) + 127u) & ~127u;
    int b = blockIdx.z, bm = blockIdx.y * 128, bn = blockIdx.x * 128;
    const __half* Ah = g_Sh + ((size_t)b * P + bm) * COUT;
    const __half* Bh = g_Sh + ((size_t)(4 + b) * P + bn) * COUT;
    float acc[2][8][4] = {};
    gemm_ml(smb, Ah, Bh, COUT, COUT, COUT, acc);

    if (threadIdx.x < 128) { su[threadIdx.x] = 0u; tu[threadIdx.x] = 0u; }
    __syncthreads();

    int lane = threadIdx.x & 31, wid = threadIdx.x >> 5, wm = wid & 3, wn = wid >> 2;
    const float* ssums = g_ssum + b * P;
    const float* ssumt = g_ssum + (4 + b) * P;
    float* C = g_corr + (size_t)b * P * P;
#pragma unroll
    for (int i = 0; i < 2; i++) {
        int sl0 = wm * 32 + i * 16 + (lane >> 2);
        int s0 = bm + sl0;
        float is0 = rsqrtf(ssums[s0] + 1e-6f), is1 = rsqrtf(ssums[s0 + 8] + 1e-6f);
        unsigned ks0 = 0u, ks1 = 0u;
#pragma unroll
        for (int j = 0; j < 8; j++) {
            int tl0 = wn * 64 + j * 8 + 2 * (lane & 3);
            int t0 = bn + tl0;
            float it0 = rsqrtf(ssumt[t0] + 1e-6f), it1 = rsqrtf(ssumt[t0 + 1] + 1e-6f);
            float c00 = acc[i][j][0] * is0 * it0;
            float c01 = acc[i][j][1] * is0 * it1;
            float c10 = acc[i][j][2] * is1 * it0;
            float c11 = acc[i][j][3] * is1 * it1;
            C[(size_t)t0 * P + s0]           = c00;
            C[(size_t)(t0 + 1) * P + s0]     = c01;
            C[(size_t)t0 * P + s0 + 8]       = c10;
            C[(size_t)(t0 + 1) * P + s0 + 8] = c11;
            unsigned k00 = fkey(c00), k01 = fkey(c01), k10 = fkey(c10), k11 = fkey(c11);
            ks0 = max(ks0, max(k00, k01));
            ks1 = max(ks1, max(k10, k11));
            atomicMax(&tu[tl0],     max(k00, k10));
            atomicMax(&tu[tl0 + 1], max(k01, k11));
        }
        atomicMax(&su[sl0], ks0);
        atomicMax(&su[sl0 + 8], ks1);
    }
    __syncthreads();
    if (threadIdx.x < 128) {
        atomicMax(&g_smaxu[b * P + bm + threadIdx.x], su[threadIdx.x]);
        atomicMax(&g_tmaxu[b * P + bn + threadIdx.x], tu[threadIdx.x]);
    }
}

// ---------------- fused filter + resize + softmax + soft-argmax + flow ----------------
__global__ void __launch_bounds__(256) k_flow(float* __restrict__ out) {
    int tx = blockIdx.x, ty = blockIdx.y, b = blockIdx.z;
    int tid = threadIdx.x;
    const float sc = 31.f / 63.f;
    float fy = ty * sc; int y0 = (int)fy; int y1 = min(y0 + 1, 31); float wy = fy - (float)y0;
    float fx = tx * sc; int x0 = (int)fx; int x1 = min(x0 + 1, 31); float wx = fx - (float)x0;
    int t00 = y0 * 32 + x0, t01 = y0 * 32 + x1, t10 = y1 * 32 + x0, t11 = y1 * 32 + x1;
    const float* C = g_corr + (size_t)b * P * P;
    const float* r00 = C + (size_t)t00 * P;
    const float* r01 = C + (size_t)t01 * P;
    const float* r10 = C + (size_t)t10 * P;
    const float* r11 = C + (size_t)t11 * P;
    float tm00 = funkey(g_tmaxu[b * P + t00]); if (tm00 == 0.f) tm00 = 1e-30f;
    float tm01 = funkey(g_tmaxu[b * P + t01]); if (tm01 == 0.f) tm01 = 1e-30f;
    float tm10 = funkey(g_tmaxu[b * P + t10]); if (tm10 == 0.f) tm10 = 1e-30f;
    float tm11 = funkey(g_tmaxu[b * P + t11]); if (tm11 == 0.f) tm11 = 1e-30f;
    float ww00 = (1.f - wy) * (1.f - wx) / tm00;
    float ww01 = (1.f - wy) * wx         / tm01;
    float ww10 = wy * (1.f - wx)         / tm10;
    float ww11 = wy * wx                 / tm11;

    __shared__ float m[P];
    __shared__ float rowt[32][64];
    __shared__ float rd[8], rs[8], rx[8], ry[8];

    float mx;
    {
        int s0 = tid * 4;
        float4 v00 = *(const float4*)(r00 + s0);
        float4 v01 = *(const float4*)(r01 + s0);
        float4 v10 = *(const float4*)(r10 + s0);
        float4 v11 = *(const float4*)(r11 + s0);
        uint4 km = *(const uint4*)(g_smaxu + (size_t)b * P + s0);
        float sm0 = funkey(km.x); if (sm0 == 0.f) sm0 = 1e-30f;
        float sm1 = funkey(km.y); if (sm1 == 0.f) sm1 = 1e-30f;
        float sm2 = funkey(km.z); if (sm2 == 0.f) sm2 = 1e-30f;
        float sm3 = funkey(km.w); if (sm3 == 0.f) sm3 = 1e-30f;
        float4 mv;
        mv.x = __fdividef(ww00 * v00.x * v00.x * v00.x + ww01 * v01.x * v01.x * v01.x
              + ww10 * v10.x * v10.x * v10.x + ww11 * v11.x * v11.x * v11.x, sm0);
        mv.y = __fdividef(ww00 * v00.y * v00.y * v00.y + ww01 * v01.y * v01.y * v01.y
              + ww10 * v10.y * v10.y * v10.y + ww11 * v11.y * v11.y * v11.y, sm1);
        mv.z = __fdividef(ww00 * v00.z * v00.z * v00.z + ww01 * v01.z * v01.z * v01.z
              + ww10 * v10.z * v10.z * v10.z + ww11 * v11.z * v11.z * v11.z, sm2);
        mv.w = __fdividef(ww00 * v00.w * v00.w * v00.w + ww01 * v01.w * v01.w * v01.w
              + ww10 * v10.w * v10.w * v10.w + ww11 * v11.w * v11.w * v11.w, sm3);
        *(float4*)(m + s0) = mv;
        mx = fmaxf(fmaxf(mv.x, mv.y), fmaxf(mv.z, mv.w));
    }
#pragma unroll
    for (int o = 16; o > 0; o >>= 1) mx = fmaxf(mx, __shfl_xor_sync(0xffffffffu, mx, o));
    if ((tid & 31) == 0) rd[tid >> 5] = mx;
    __syncthreads();

    for (int idx = tid; idx < 32 * 64; idx += 256) {
        int y = idx >> 6, j = idx & 63;
        float gx = j * sc; int xx0 = (int)gx; int xx1 = min(xx0 + 1, 31); float bq = gx - (float)xx0;
        float u0 = m[y * 32 + xx0];
        rowt[y][j] = u0 + bq * (m[y * 32 + xx1] - u0);
    }
    float M = -INFINITY;
#pragma unroll
    for (int i = 0; i < 8; i++) M = fmaxf(M, rd[i]);
    __syncthreads();

    int j = tid & 63, i0 = tid >> 6;
    float xn = -1.f + j * (2.f / 63.f);
    float sum = 0.f, sx = 0.f, sy = 0.f;
#pragma unroll
    for (int k2 = 0; k2 < 16; k2++) {
        int i = i0 + k2 * 4;
        float gy = i * sc; int yy0 = (int)gy; int yy1 = min(yy0 + 1, 31); float a = gy - (float)yy0;
        float u0 = rowt[yy0][j];
        float v = u0 + a * (rowt[yy1][j] - u0);
        float e = __expf((v - M) * 50.f);
        sum += e;
        sx = fmaf(e, xn, sx);
        sy = fmaf(e, -1.f + i * (2.f / 63.f), sy);
    }
#pragma unroll
    for (int o = 16; o > 0; o >>= 1) {
        sum += __shfl_xor_sync(0xffffffffu, sum, o);
        sx  += __shfl_xor_sync(0xffffffffu, sx,  o);
        sy  += __shfl_xor_sync(0xffffffffu, sy,  o);
    }
    if ((tid & 31) == 0) { rs[tid >> 5] = sum; rx[tid >> 5] = sx; ry[tid >> 5] = sy; }
    __syncthreads();
    if (tid == 0) {
        float S = 0.f, X = 0.f, Y = 0.f;
#pragma unroll
        for (int i = 0; i < 8; i++) { S += rs[i]; X += rx[i]; Y += ry[i]; }
        float gx_ = X / S, gy_ = Y / S;
        out[(size_t)b * 8192 + (size_t)ty * 64 + tx]        = (gx_ + 1.f) * 31.5f - (float)tx;
        out[(size_t)b * 8192 + 4096 + (size_t)ty * 64 + tx] = (gy_ + 1.f) * 31.5f - (float)ty;
    }
}

// ---------------- launch ----------------
extern "C" void kernel_launch(void* const* d_in, const int* in_sizes, int n_in,
                              void* d_out, int out_size) {
    const float* src  = (const float*)d_in[0];
    const float* tgt  = (const float*)d_in[1];
    const float* W    = (const float*)d_in[2];
    const float* bias = (const float*)d_in[3];
    float* out = (float*)d_out;

    cudaFuncSetAttribute(k_pre,  cudaFuncAttributeMaxDynamicSharedMemorySize, PREB);
    cudaFuncSetAttribute(k_conv, cudaFuncAttributeMaxDynamicSharedMemorySize, SMEMB);
    cudaFuncSetAttribute(k_corr, cudaFuncAttributeMaxDynamicSharedMemorySize, SMEMB);

    k_wpad <<<1088, 256>>>(W);
    k_pre  <<<dim3(8, 32), 256, PREB>>>(src, tgt);
    k_conv <<<296, 256, SMEMB>>>(bias);
    k_corr <<<dim3(8, 8, 4), 256, SMEMB>>>();
    k_flow <<<dim3(64, 64, 4), 256>>>(out);
}